// round 12
// baseline (speedup 1.0000x reference)
#include <cuda_runtime.h>
#include <cuda_fp16.h>

#define N_NODES 100000
#define N_EDGES 1000000
#define HID 64
#define CAP 64          // ELL capacity per node (P(deg>64) ~ 1e-40 at mean 10)

#define GT 256          // nodes per GEMM block tile
#define WLD 68          // padded W row
#define SMEM_GEMM ((HID * GT + HID * WLD) * 4)        // 82944 B

// Scratch (device globals: allocation-free per harness rules)
__device__ __align__(16) __half g_half[N_NODES * HID]; // transform out, fp16 (gather source)
__device__ __align__(16) float h_buf[N_NODES * HID];   // aggregated layer output (fp32)
__device__ __align__(16) float px_buf[N_NODES * 2];    // dinv * x
__device__ __align__(16) float t_buf[N_NODES * 2];     // conv1 scatter accumulator (width 2)
__device__ float dinv_buf[N_NODES];
__device__ int   cur_deg[N_NODES];                     // fill cursor == degree after fill
__device__ int   ell_row[N_NODES * CAP];               // source nodes, ELL layout

// ---------------- f32x2 packed helpers ----------------
__device__ __forceinline__ unsigned long long ffma2(unsigned long long a,
                                                    unsigned long long b,
                                                    unsigned long long c) {
    unsigned long long d;
    asm("fma.rn.f32x2 %0, %1, %2, %3;" : "=l"(d) : "l"(a), "l"(b), "l"(c));
    return d;
}
__device__ __forceinline__ unsigned long long bcast2(float x) {
    unsigned long long d;
    asm("mov.b64 %0, {%1, %1};" : "=l"(d) : "f"(x));
    return d;
}
__device__ __forceinline__ float2 unpk(unsigned long long v) {
    float lo, hi;
    asm("mov.b64 {%0, %1}, %2;" : "=f"(lo), "=f"(hi) : "l"(v));
    return make_float2(lo, hi);
}

// ---------------- ELL build ----------------
__global__ void k_zero() {
    int i = blockIdx.x * blockDim.x + threadIdx.x;
    if (i < N_NODES) {
        cur_deg[i] = 0;
        ((float2*)t_buf)[i] = make_float2(0.f, 0.f);
    }
}

__global__ void k_fill(const int* __restrict__ ei) {
    int e2 = (blockIdx.x * blockDim.x + threadIdx.x) * 2;
    if (e2 < N_EDGES) {
        int2 r = *(const int2*)(ei + e2);
        int2 c = *(const int2*)(ei + N_EDGES + e2);
        int p0 = atomicAdd(&cur_deg[c.x], 1);
        if (p0 < CAP) ell_row[c.x * CAP + p0] = r.x;
        int p1 = atomicAdd(&cur_deg[c.y], 1);
        if (p1 < CAP) ell_row[c.y * CAP + p1] = r.y;
    }
}

__global__ void k_prep(const float* __restrict__ x) {
    int i = blockIdx.x * blockDim.x + threadIdx.x;
    if (i < N_NODES) {
        int d = cur_deg[i];
        float di = rsqrtf((float)(d + 1));     // +1 self loop
        dinv_buf[i] = di;
        float2 xv = ((const float2*)x)[i];
        ((float2*)px_buf)[i] = make_float2(di * xv.x, di * xv.y);
    }
}

// ---------------- conv1 aggregation by scatter: t[c] += px[r] ----------------
__global__ void k_scatter2(const int* __restrict__ ei) {
    int e2 = (blockIdx.x * blockDim.x + threadIdx.x) * 2;
    if (e2 < N_EDGES) {
        int2 r = *(const int2*)(ei + e2);
        int2 c = *(const int2*)(ei + N_EDGES + e2);
        const float2* pp = (const float2*)px_buf;
        float2 v0 = __ldg(&pp[r.x]);
        float2 v1 = __ldg(&pp[r.y]);
        float* d0 = t_buf + c.x * 2;
        float* d1 = t_buf + c.y * 2;
        asm volatile("red.global.add.v2.f32 [%0], {%1,%2};"
                     :: "l"(d0), "f"(v0.x), "f"(v0.y) : "memory");
        asm volatile("red.global.add.v2.f32 [%0], {%1,%2};"
                     :: "l"(d1), "f"(v1.x), "f"(v1.y) : "memory");
    }
}

// ---------------- fused gather-aggregate + finalize (fp16 source, fp32 accum) ----
// h[i] = relu?( dinv[i] * (g[i] + sum_{j in N(i)} g[j]) + b )
__global__ void k_gather(const float* __restrict__ bias, int do_relu) {
    int w = (blockIdx.x * blockDim.x + threadIdx.x) >> 5;
    int lane = threadIdx.x & 31;
    if (w >= N_NODES) return;

    const __half2* gp = (const __half2*)g_half;
    float2 acc = __half22float2(gp[w * 32 + lane]);   // self loop
    int s = w * CAP;
    int d = cur_deg[w]; if (d > CAP) d = CAP;
    int e = s + d;

    int k = s;
    for (; k + 8 <= e; k += 8) {
        int r0 = ell_row[k],   r1 = ell_row[k+1], r2 = ell_row[k+2], r3 = ell_row[k+3];
        int r4 = ell_row[k+4], r5 = ell_row[k+5], r6 = ell_row[k+6], r7 = ell_row[k+7];
        float2 v0 = __half22float2(__ldg(&gp[r0 * 32 + lane]));
        float2 v1 = __half22float2(__ldg(&gp[r1 * 32 + lane]));
        float2 v2 = __half22float2(__ldg(&gp[r2 * 32 + lane]));
        float2 v3 = __half22float2(__ldg(&gp[r3 * 32 + lane]));
        float2 v4 = __half22float2(__ldg(&gp[r4 * 32 + lane]));
        float2 v5 = __half22float2(__ldg(&gp[r5 * 32 + lane]));
        float2 v6 = __half22float2(__ldg(&gp[r6 * 32 + lane]));
        float2 v7 = __half22float2(__ldg(&gp[r7 * 32 + lane]));
        acc.x += ((v0.x + v1.x) + (v2.x + v3.x)) + ((v4.x + v5.x) + (v6.x + v7.x));
        acc.y += ((v0.y + v1.y) + (v2.y + v3.y)) + ((v4.y + v5.y) + (v6.y + v7.y));
    }
    for (; k < e; k++) {
        float2 v = __half22float2(__ldg(&gp[ell_row[k] * 32 + lane]));
        acc.x += v.x;
        acc.y += v.y;
    }

    float di = dinv_buf[w];
    float o0 = di * acc.x + bias[lane * 2];
    float o1 = di * acc.y + bias[lane * 2 + 1];
    if (do_relu) { o0 = fmaxf(o0, 0.f); o1 = fmaxf(o1, 0.f); }
    ((float2*)h_buf)[w * 32 + lane] = make_float2(o0, o1);
}

// ---------------- GEMM helpers (k-major Xs, FFMA2 core) ----------------
__device__ __forceinline__ void load_W(const float* __restrict__ W, float* Ws) {
    for (int i = threadIdx.x; i < HID * HID / 4; i += 256) {
        float4 w4 = ((const float4*)W)[i];
        int k = (i * 4) >> 6, f = (i * 4) & 63;
        *(float4*)(Ws + k * WLD + f) = w4;
    }
}

__device__ __forceinline__ void load_X_T(int base, float* Xs) {
    int tid = threadIdx.x;
    int node = base + tid;
    if (node < N_NODES) {
        const float4* src = (const float4*)(h_buf + node * HID);
#pragma unroll
        for (int kk = 0; kk < 16; kk++) {
            float4 v = src[kk];
            Xs[(kk * 4 + 0) * GT + tid] = v.x;
            Xs[(kk * 4 + 1) * GT + tid] = v.y;
            Xs[(kk * 4 + 2) * GT + tid] = v.z;
            Xs[(kk * 4 + 3) * GT + tid] = v.w;
        }
    } else {
#pragma unroll
        for (int kk = 0; kk < HID; kk++) Xs[kk * GT + tid] = 0.f;
    }
}

// acc2[p*8+j] = packed (out[n=tm*8+2p][f=tn*8+j], out[n=tm*8+2p+1][f=tn*8+j])
__device__ __forceinline__ void gemm_core_f2(const float* Xs, const float* Ws,
                                             unsigned long long* acc2) {
    int tid = threadIdx.x;
    int tn = tid & 7, tm = tid >> 3;
    const float* xbase = Xs + tm * 8;
    const float* wbase = Ws + tn * 8;
#pragma unroll 4
    for (int k = 0; k < HID; k++) {
        union { float4 f; unsigned long long u[2]; } xa, xb;
        xa.f = *(const float4*)(xbase + k * GT);
        xb.f = *(const float4*)(xbase + k * GT + 4);
        float4 wa = *(const float4*)(wbase + k * WLD);
        float4 wb = *(const float4*)(wbase + k * WLD + 4);
        float wr[8] = {wa.x, wa.y, wa.z, wa.w, wb.x, wb.y, wb.z, wb.w};
#pragma unroll
        for (int j = 0; j < 8; j++) {
            unsigned long long wj = bcast2(wr[j]);
            acc2[0*8+j] = ffma2(xa.u[0], wj, acc2[0*8+j]);
            acc2[1*8+j] = ffma2(xa.u[1], wj, acc2[1*8+j]);
            acc2[2*8+j] = ffma2(xb.u[0], wj, acc2[2*8+j]);
            acc2[3*8+j] = ffma2(xb.u[1], wj, acc2[3*8+j]);
        }
    }
}

// conv epilogue: g_half[n][f] = (half)(dinv[n] * acc)
__device__ __forceinline__ void conv_epilogue(int base, const unsigned long long* acc2) {
    int tid = threadIdx.x;
    int tn = tid & 7, tm = tid >> 3;
    __half2* gp = (__half2*)g_half;
#pragma unroll
    for (int p = 0; p < 4; p++) {
        float lo[8], hi[8];
#pragma unroll
        for (int j = 0; j < 8; j++) {
            float2 v = unpk(acc2[p*8+j]);
            lo[j] = v.x; hi[j] = v.y;
        }
        int n0 = base + tm * 8 + 2 * p;
        int n1 = n0 + 1;
        if (n0 < N_NODES) {
            float d0 = dinv_buf[n0];
            gp[n0 * 32 + tn * 4 + 0] = __floats2half2_rn(lo[0]*d0, lo[1]*d0);
            gp[n0 * 32 + tn * 4 + 1] = __floats2half2_rn(lo[2]*d0, lo[3]*d0);
            gp[n0 * 32 + tn * 4 + 2] = __floats2half2_rn(lo[4]*d0, lo[5]*d0);
            gp[n0 * 32 + tn * 4 + 3] = __floats2half2_rn(lo[6]*d0, lo[7]*d0);
        }
        if (n1 < N_NODES) {
            float d1 = dinv_buf[n1];
            gp[n1 * 32 + tn * 4 + 0] = __floats2half2_rn(hi[0]*d1, hi[1]*d1);
            gp[n1 * 32 + tn * 4 + 1] = __floats2half2_rn(hi[2]*d1, hi[3]*d1);
            gp[n1 * 32 + tn * 4 + 2] = __floats2half2_rn(hi[4]*d1, hi[5]*d1);
            gp[n1 * 32 + tn * 4 + 3] = __floats2half2_rn(hi[6]*d1, hi[7]*d1);
        }
    }
}

// ---------------- conv2: finalize t + expand via W1 in-reg -> k-major smem; GEMM W2
__global__ __launch_bounds__(256, 2) void k_conv2(const float* __restrict__ W1,
                                                  const float* __restrict__ b1,
                                                  const float* __restrict__ W2) {
    extern __shared__ float sm[];
    float* Xs = sm;
    float* Ws = sm + HID * GT;
    __shared__ float W1s[192];
    int tid = threadIdx.x;
    int base = blockIdx.x * GT;

    if (tid < 128) W1s[tid] = W1[tid];
    else if (tid < 192) W1s[tid] = b1[tid - 128];
    load_W(W2, Ws);

    float2 t = make_float2(0.f, 0.f);
    int node = base + tid;
    bool valid = node < N_NODES;
    if (valid) {
        float2 ts = ((const float2*)t_buf)[node];     // scattered neighbor sum
        float2 ps = ((const float2*)px_buf)[node];    // self loop
        float di = dinv_buf[node];
        t = make_float2(di * (ts.x + ps.x), di * (ts.y + ps.y));
    }
    __syncthreads();
#pragma unroll
    for (int k = 0; k < HID; k++) {
        float v = valid ? fmaxf(t.x * W1s[k] + t.y * W1s[64 + k] + W1s[128 + k], 0.f) : 0.f;
        Xs[k * GT + tid] = v;
    }
    __syncthreads();

    unsigned long long acc2[32];
#pragma unroll
    for (int i = 0; i < 32; i++) acc2[i] = 0ULL;
    gemm_core_f2(Xs, Ws, acc2);
    conv_epilogue(base, acc2);
}

// ---------------- conv3: X from h_buf; GEMM W3; g = dinv * X@W3 ------------------
__global__ __launch_bounds__(256, 2) void k_conv3(const float* __restrict__ W3) {
    extern __shared__ float sm[];
    float* Xs = sm;
    float* Ws = sm + HID * GT;
    int base = blockIdx.x * GT;

    load_W(W3, Ws);
    load_X_T(base, Xs);
    __syncthreads();

    unsigned long long acc2[32];
#pragma unroll
    for (int i = 0; i < 32; i++) acc2[i] = 0ULL;
    gemm_core_f2(Xs, Ws, acc2);
    conv_epilogue(base, acc2);
}

// ---------------- l45: X from h_buf; GEMM W4; out = relu(acc+b4) . W5 + b5 -------
__global__ __launch_bounds__(256, 2) void k_l45(const float* __restrict__ W4,
                                                const float* __restrict__ b4,
                                                const float* __restrict__ W5,
                                                const float* __restrict__ b5,
                                                float* __restrict__ out) {
    extern __shared__ float sm[];
    float* Xs = sm;
    float* Ws = sm + HID * GT;
    int tid = threadIdx.x;
    int base = blockIdx.x * GT;

    load_W(W4, Ws);
    load_X_T(base, Xs);
    __syncthreads();

    unsigned long long acc2[32];
#pragma unroll
    for (int i = 0; i < 32; i++) acc2[i] = 0ULL;
    gemm_core_f2(Xs, Ws, acc2);

    int tn = tid & 7, tm = tid >> 3;
    float4 b4a = __ldg((const float4*)(b4 + tn * 8));
    float4 b4b = __ldg((const float4*)(b4 + tn * 8 + 4));
    float4 w5a = __ldg((const float4*)(W5 + tn * 8));
    float4 w5b = __ldg((const float4*)(W5 + tn * 8 + 4));
    float br[8] = {b4a.x, b4a.y, b4a.z, b4a.w, b4b.x, b4b.y, b4b.z, b4b.w};
    float wr[8] = {w5a.x, w5a.y, w5a.z, w5a.w, w5b.x, w5b.y, w5b.z, w5b.w};
    float bias5 = __ldg(b5);

#pragma unroll
    for (int p = 0; p < 4; p++) {
        float v0 = 0.f, v1 = 0.f;
#pragma unroll
        for (int j = 0; j < 8; j++) {
            float2 v = unpk(acc2[p*8+j]);
            v0 += fmaxf(v.x + br[j], 0.f) * wr[j];
            v1 += fmaxf(v.y + br[j], 0.f) * wr[j];
        }
        v0 += __shfl_xor_sync(0xffffffffu, v0, 1);
        v0 += __shfl_xor_sync(0xffffffffu, v0, 2);
        v0 += __shfl_xor_sync(0xffffffffu, v0, 4);
        v1 += __shfl_xor_sync(0xffffffffu, v1, 1);
        v1 += __shfl_xor_sync(0xffffffffu, v1, 2);
        v1 += __shfl_xor_sync(0xffffffffu, v1, 4);
        if (tn == 0) {
            int n0 = base + tm * 8 + 2 * p;
            if (n0 < N_NODES)     out[n0]     = v0 + bias5;
            if (n0 + 1 < N_NODES) out[n0 + 1] = v1 + bias5;
        }
    }
}

extern "C" void kernel_launch(void* const* d_in, const int* in_sizes, int n_in,
                              void* d_out, int out_size) {
    const float* x  = (const float*)d_in[0];
    const int*   ei = (const int*)d_in[1];     // edge_index int32
    const float* W1 = (const float*)d_in[3];
    const float* b1 = (const float*)d_in[4];
    const float* W2 = (const float*)d_in[5];
    const float* b2 = (const float*)d_in[6];
    const float* W3 = (const float*)d_in[7];
    const float* b3 = (const float*)d_in[8];
    const float* W4 = (const float*)d_in[9];
    const float* b4 = (const float*)d_in[10];
    const float* W5 = (const float*)d_in[11];
    const float* b5 = (const float*)d_in[12];
    float* out = (float*)d_out;

    static int smem_set = 0;
    if (!smem_set) {
        cudaFuncSetAttribute(k_conv2, cudaFuncAttributeMaxDynamicSharedMemorySize, SMEM_GEMM);
        cudaFuncSetAttribute(k_conv3, cudaFuncAttributeMaxDynamicSharedMemorySize, SMEM_GEMM);
        cudaFuncSetAttribute(k_l45,   cudaFuncAttributeMaxDynamicSharedMemorySize, SMEM_GEMM);
        smem_set = 1;
    }

    const int nbN  = (N_NODES + 255) / 256;
    const int nbE2 = (N_EDGES / 2 + 255) / 256;
    const int nbG  = (N_NODES + GT - 1) / GT;          // 391
    const int nbW  = (N_NODES * 32 + 255) / 256;       // 1 warp per node

    // ELL build: zero cursors+t -> fill (cursor becomes degree) -> dinv/px prep
    k_zero<<<nbN, 256>>>();
    k_fill<<<nbE2, 256>>>(ei);
    k_prep<<<nbN, 256>>>(x);

    // conv1 aggregation by width-2 scatter (red.add.v2)
    k_scatter2<<<nbE2, 256>>>(ei);

    // conv2: finalize t + expand + GEMM -> g(half) ; gather -> h
    k_conv2<<<nbG, 256, SMEM_GEMM>>>(W1, b1, W2);
    k_gather<<<nbW, 256>>>(b2, 1);
    // conv3: GEMM -> g(half) ; gather -> h
    k_conv3<<<nbG, 256, SMEM_GEMM>>>(W3);
    k_gather<<<nbW, 256>>>(b3, 0);
    // layers 4+5 fused
    k_l45<<<nbG, 256, SMEM_GEMM>>>(W4, b4, W5, b5, out);
}

// round 14
// speedup vs baseline: 1.2057x; 1.2057x over previous
#include <cuda_runtime.h>
#include <cuda_fp16.h>
#include <cstdint>

#define N_NODES 100000
#define N_EDGES 1000000
#define HID 64
#define CAP 64          // ELL capacity per node (P(deg>64) ~ 1e-40 at mean 10)

#define GT 256          // nodes per GEMM block tile
#define XLD 264         // Xs row stride (floats): bank-conflict-free fragment loads
#define WLD 72          // Ws row stride
#define SMEM_GEMM ((HID * XLD + HID * WLD) * 4)       // 86016 B

// Scratch (device globals: allocation-free per harness rules)
__device__ __align__(16) __half g_half[N_NODES * HID]; // transform out, fp16 (gather source)
__device__ __align__(16) float h_buf[N_NODES * HID];   // aggregated layer output (fp32)
__device__ __align__(16) float px_buf[N_NODES * 2];    // dinv * x
__device__ __align__(16) float t_buf[N_NODES * 2];     // conv1 aggregated (width 2)
__device__ float dinv_buf[N_NODES];
__device__ int   cur_deg[N_NODES];                     // fill cursor == degree after fill
__device__ int   ell_row[N_NODES * CAP];               // source nodes, ELL layout

// ---------------- tf32 helpers ----------------
__device__ __forceinline__ float f2tf32f(float f) {
    uint32_t r;
    asm("cvt.rna.tf32.f32 %0, %1;" : "=r"(r) : "f"(f));
    return __uint_as_float(r);
}
// D += A(16x8,row) * B(8x8,col) ; tf32 inputs, f32 accum
__device__ __forceinline__ void mma_tf32(float* c, const uint32_t* a,
                                         uint32_t b0, uint32_t b1) {
    asm("mma.sync.aligned.m16n8k8.row.col.f32.tf32.tf32.f32 "
        "{%0,%1,%2,%3}, {%4,%5,%6,%7}, {%8,%9}, {%0,%1,%2,%3};"
        : "+f"(c[0]), "+f"(c[1]), "+f"(c[2]), "+f"(c[3])
        : "r"(a[0]), "r"(a[1]), "r"(a[2]), "r"(a[3]), "r"(b0), "r"(b1));
}

// ---------------- ELL build ----------------
__global__ void k_zero() {
    int i = blockIdx.x * blockDim.x + threadIdx.x;
    if (i < N_NODES) cur_deg[i] = 0;
}

__global__ void k_fill(const int* __restrict__ ei) {
    int e2 = (blockIdx.x * blockDim.x + threadIdx.x) * 2;
    if (e2 < N_EDGES) {
        int2 r = *(const int2*)(ei + e2);
        int2 c = *(const int2*)(ei + N_EDGES + e2);
        int p0 = atomicAdd(&cur_deg[c.x], 1);
        if (p0 < CAP) ell_row[c.x * CAP + p0] = r.x;
        int p1 = atomicAdd(&cur_deg[c.y], 1);
        if (p1 < CAP) ell_row[c.y * CAP + p1] = r.y;
    }
}

__global__ void k_prep(const float* __restrict__ x) {
    int i = blockIdx.x * blockDim.x + threadIdx.x;
    if (i < N_NODES) {
        int d = cur_deg[i];
        float di = rsqrtf((float)(d + 1));     // +1 self loop
        dinv_buf[i] = di;
        float2 xv = ((const float2*)x)[i];
        ((float2*)px_buf)[i] = make_float2(di * xv.x, di * xv.y);
    }
}

// ---------------- width-2 aggregation for conv1 ----------------
__global__ void k_gather2() {
    int i = blockIdx.x * blockDim.x + threadIdx.x;
    if (i < N_NODES) {
        const float2* pp = (const float2*)px_buf;
        float2 acc = pp[i];                    // self loop
        int s = i * CAP;
        int d = cur_deg[i]; if (d > CAP) d = CAP;
        int e = s + d;
        int k = s;
        for (; k + 4 <= e; k += 4) {
            int r0 = ell_row[k], r1 = ell_row[k+1], r2 = ell_row[k+2], r3 = ell_row[k+3];
            float2 v0 = __ldg(&pp[r0]), v1 = __ldg(&pp[r1]);
            float2 v2 = __ldg(&pp[r2]), v3 = __ldg(&pp[r3]);
            acc.x += v0.x + v1.x + v2.x + v3.x;
            acc.y += v0.y + v1.y + v2.y + v3.y;
        }
        for (; k < e; k++) {
            float2 v = __ldg(&pp[ell_row[k]]);
            acc.x += v.x; acc.y += v.y;
        }
        float di = dinv_buf[i];
        ((float2*)t_buf)[i] = make_float2(di * acc.x, di * acc.y);
    }
}

// ---------------- fused gather-aggregate + finalize (fp16 source, fp32 accum) ----
__global__ void k_gather(const float* __restrict__ bias, int do_relu) {
    int w = (blockIdx.x * blockDim.x + threadIdx.x) >> 5;
    int lane = threadIdx.x & 31;
    if (w >= N_NODES) return;

    const __half2* gp = (const __half2*)g_half;
    float2 acc = __half22float2(gp[w * 32 + lane]);   // self loop
    int s = w * CAP;
    int d = cur_deg[w]; if (d > CAP) d = CAP;
    int e = s + d;

    int k = s;
    for (; k + 8 <= e; k += 8) {
        int r0 = ell_row[k],   r1 = ell_row[k+1], r2 = ell_row[k+2], r3 = ell_row[k+3];
        int r4 = ell_row[k+4], r5 = ell_row[k+5], r6 = ell_row[k+6], r7 = ell_row[k+7];
        float2 v0 = __half22float2(__ldg(&gp[r0 * 32 + lane]));
        float2 v1 = __half22float2(__ldg(&gp[r1 * 32 + lane]));
        float2 v2 = __half22float2(__ldg(&gp[r2 * 32 + lane]));
        float2 v3 = __half22float2(__ldg(&gp[r3 * 32 + lane]));
        float2 v4 = __half22float2(__ldg(&gp[r4 * 32 + lane]));
        float2 v5 = __half22float2(__ldg(&gp[r5 * 32 + lane]));
        float2 v6 = __half22float2(__ldg(&gp[r6 * 32 + lane]));
        float2 v7 = __half22float2(__ldg(&gp[r7 * 32 + lane]));
        acc.x += ((v0.x + v1.x) + (v2.x + v3.x)) + ((v4.x + v5.x) + (v6.x + v7.x));
        acc.y += ((v0.y + v1.y) + (v2.y + v3.y)) + ((v4.y + v5.y) + (v6.y + v7.y));
    }
    for (; k < e; k++) {
        float2 v = __half22float2(__ldg(&gp[ell_row[k] * 32 + lane]));
        acc.x += v.x;
        acc.y += v.y;
    }

    float di = dinv_buf[w];
    float o0 = di * acc.x + bias[lane * 2];
    float o1 = di * acc.y + bias[lane * 2 + 1];
    if (do_relu) { o0 = fmaxf(o0, 0.f); o1 = fmaxf(o1, 0.f); }
    ((float2*)h_buf)[w * 32 + lane] = make_float2(o0, o1);
}

// ---------------- GEMM helpers (tf32 in smem, mma.m16n8k8 core) ----------------
__device__ __forceinline__ void load_W(const float* __restrict__ W, float* Ws) {
    for (int i = threadIdx.x; i < HID * HID / 4; i += 256) {
        float4 w4 = ((const float4*)W)[i];
        int k = (i * 4) >> 6, f = (i * 4) & 63;
        float* dst = Ws + k * WLD + f;
        dst[0] = f2tf32f(w4.x);
        dst[1] = f2tf32f(w4.y);
        dst[2] = f2tf32f(w4.z);
        dst[3] = f2tf32f(w4.w);
    }
}

__device__ __forceinline__ void load_X_T(int base, float* Xs) {
    int tid = threadIdx.x;
    int node = base + tid;
    if (node < N_NODES) {
        const float4* src = (const float4*)(h_buf + node * HID);
#pragma unroll
        for (int kk = 0; kk < 16; kk++) {
            float4 v = src[kk];
            Xs[(kk * 4 + 0) * XLD + tid] = f2tf32f(v.x);
            Xs[(kk * 4 + 1) * XLD + tid] = f2tf32f(v.y);
            Xs[(kk * 4 + 2) * XLD + tid] = f2tf32f(v.z);
            Xs[(kk * 4 + 3) * XLD + tid] = f2tf32f(v.w);
        }
    } else {
#pragma unroll
        for (int kk = 0; kk < HID; kk++) Xs[kk * XLD + tid] = 0.f;
    }
}

// acc[mt][nt][4]: rows (w*32+mt*16+qr, +8), cols (nt*8+2qc, +1)
__device__ __forceinline__ void mma_core(const float* Xs, const float* Ws,
                                         float acc[2][8][4]) {
    int lane = threadIdx.x & 31, w = threadIdx.x >> 5;
    int qr = lane >> 2;       // 0..7
    int qc = lane & 3;        // 0..3
#pragma unroll
    for (int ks = 0; ks < 8; ks++) {
        uint32_t a[2][4];
#pragma unroll
        for (int mt = 0; mt < 2; mt++) {
            int rb = w * 32 + mt * 16 + qr;
            a[mt][0] = __float_as_uint(Xs[(ks * 8 + qc) * XLD + rb]);
            a[mt][1] = __float_as_uint(Xs[(ks * 8 + qc) * XLD + rb + 8]);
            a[mt][2] = __float_as_uint(Xs[(ks * 8 + qc + 4) * XLD + rb]);
            a[mt][3] = __float_as_uint(Xs[(ks * 8 + qc + 4) * XLD + rb + 8]);
        }
#pragma unroll
        for (int nt = 0; nt < 8; nt++) {
            uint32_t b0 = __float_as_uint(Ws[(ks * 8 + qc) * WLD + nt * 8 + qr]);
            uint32_t b1 = __float_as_uint(Ws[(ks * 8 + qc + 4) * WLD + nt * 8 + qr]);
            mma_tf32(acc[0][nt], a[0], b0, b1);
            mma_tf32(acc[1][nt], a[1], b0, b1);
        }
    }
}

// conv epilogue: g_half[n][f] = (half)(dinv[n] * acc)
__device__ __forceinline__ void conv_epilogue(int base, float acc[2][8][4]) {
    int lane = threadIdx.x & 31, w = threadIdx.x >> 5;
    int qr = lane >> 2, qc = lane & 3;
    __half2* gp = (__half2*)g_half;
#pragma unroll
    for (int mt = 0; mt < 2; mt++) {
        int n0 = base + w * 32 + mt * 16 + qr;
        int n1 = n0 + 8;
        float d0 = (n0 < N_NODES) ? dinv_buf[n0] : 0.f;
        float d1 = (n1 < N_NODES) ? dinv_buf[n1] : 0.f;
#pragma unroll
        for (int nt = 0; nt < 8; nt++) {
            int f2 = nt * 4 + qc;
            if (n0 < N_NODES)
                gp[n0 * 32 + f2] = __floats2half2_rn(acc[mt][nt][0] * d0, acc[mt][nt][1] * d0);
            if (n1 < N_NODES)
                gp[n1 * 32 + f2] = __floats2half2_rn(acc[mt][nt][2] * d1, acc[mt][nt][3] * d1);
        }
    }
}

// ---------------- conv2: expand t via W1 in-reg -> tf32 smem; MMA W2 -------------
__global__ __launch_bounds__(256, 2) void k_conv2(const float* __restrict__ W1,
                                                  const float* __restrict__ b1,
                                                  const float* __restrict__ W2) {
    extern __shared__ float sm[];
    float* Xs = sm;
    float* Ws = sm + HID * XLD;
    __shared__ float W1s[192];
    int tid = threadIdx.x;
    int base = blockIdx.x * GT;

    if (tid < 128) W1s[tid] = W1[tid];
    else if (tid < 192) W1s[tid] = b1[tid - 128];
    load_W(W2, Ws);

    float2 t = make_float2(0.f, 0.f);
    int node = base + tid;
    bool valid = node < N_NODES;
    if (valid) t = ((const float2*)t_buf)[node];
    __syncthreads();
#pragma unroll
    for (int k = 0; k < HID; k++) {
        float v = valid ? fmaxf(t.x * W1s[k] + t.y * W1s[64 + k] + W1s[128 + k], 0.f) : 0.f;
        Xs[k * XLD + tid] = f2tf32f(v);
    }
    __syncthreads();

    float acc[2][8][4];
#pragma unroll
    for (int mt = 0; mt < 2; mt++)
#pragma unroll
        for (int nt = 0; nt < 8; nt++)
#pragma unroll
            for (int q = 0; q < 4; q++) acc[mt][nt][q] = 0.f;
    mma_core(Xs, Ws, acc);
    conv_epilogue(base, acc);
}

// ---------------- conv3: X from h_buf; MMA W3; g = dinv * X@W3 -------------------
__global__ __launch_bounds__(256, 2) void k_conv3(const float* __restrict__ W3) {
    extern __shared__ float sm[];
    float* Xs = sm;
    float* Ws = sm + HID * XLD;
    int base = blockIdx.x * GT;

    load_W(W3, Ws);
    load_X_T(base, Xs);
    __syncthreads();

    float acc[2][8][4];
#pragma unroll
    for (int mt = 0; mt < 2; mt++)
#pragma unroll
        for (int nt = 0; nt < 8; nt++)
#pragma unroll
            for (int q = 0; q < 4; q++) acc[mt][nt][q] = 0.f;
    mma_core(Xs, Ws, acc);
    conv_epilogue(base, acc);
}

// ---------------- l45: X from h_buf; MMA W4; out = relu(acc+b4) . W5 + b5 --------
__global__ __launch_bounds__(256, 2) void k_l45(const float* __restrict__ W4,
                                                const float* __restrict__ b4,
                                                const float* __restrict__ W5,
                                                const float* __restrict__ b5,
                                                float* __restrict__ out) {
    extern __shared__ float sm[];
    float* Xs = sm;
    float* Ws = sm + HID * XLD;
    int tid = threadIdx.x;
    int base = blockIdx.x * GT;

    load_W(W4, Ws);
    load_X_T(base, Xs);
    __syncthreads();

    float acc[2][8][4];
#pragma unroll
    for (int mt = 0; mt < 2; mt++)
#pragma unroll
        for (int nt = 0; nt < 8; nt++)
#pragma unroll
            for (int q = 0; q < 4; q++) acc[mt][nt][q] = 0.f;
    mma_core(Xs, Ws, acc);

    int lane = tid & 31, w = tid >> 5;
    int qr = lane >> 2, qc = lane & 3;
    float bias5 = __ldg(b5);

    float b4r[8][2], w5r[8][2];
#pragma unroll
    for (int nt = 0; nt < 8; nt++) {
        int f = nt * 8 + 2 * qc;
        b4r[nt][0] = __ldg(b4 + f);     b4r[nt][1] = __ldg(b4 + f + 1);
        w5r[nt][0] = __ldg(W5 + f);     w5r[nt][1] = __ldg(W5 + f + 1);
    }

#pragma unroll
    for (int mt = 0; mt < 2; mt++) {
        float s0 = 0.f, s1 = 0.f;
#pragma unroll
        for (int nt = 0; nt < 8; nt++) {
            s0 += fmaxf(acc[mt][nt][0] + b4r[nt][0], 0.f) * w5r[nt][0]
                + fmaxf(acc[mt][nt][1] + b4r[nt][1], 0.f) * w5r[nt][1];
            s1 += fmaxf(acc[mt][nt][2] + b4r[nt][0], 0.f) * w5r[nt][0]
                + fmaxf(acc[mt][nt][3] + b4r[nt][1], 0.f) * w5r[nt][1];
        }
        s0 += __shfl_xor_sync(0xffffffffu, s0, 1);
        s0 += __shfl_xor_sync(0xffffffffu, s0, 2);
        s1 += __shfl_xor_sync(0xffffffffu, s1, 1);
        s1 += __shfl_xor_sync(0xffffffffu, s1, 2);
        if (qc == 0) {
            int n0 = base + w * 32 + mt * 16 + qr;
            int n1 = n0 + 8;
            if (n0 < N_NODES) out[n0] = s0 + bias5;
            if (n1 < N_NODES) out[n1] = s1 + bias5;
        }
    }
}

extern "C" void kernel_launch(void* const* d_in, const int* in_sizes, int n_in,
                              void* d_out, int out_size) {
    const float* x  = (const float*)d_in[0];
    const int*   ei = (const int*)d_in[1];     // edge_index int32
    const float* W1 = (const float*)d_in[3];
    const float* b1 = (const float*)d_in[4];
    const float* W2 = (const float*)d_in[5];
    const float* b2 = (const float*)d_in[6];
    const float* W3 = (const float*)d_in[7];
    const float* b3 = (const float*)d_in[8];
    const float* W4 = (const float*)d_in[9];
    const float* b4 = (const float*)d_in[10];
    const float* W5 = (const float*)d_in[11];
    const float* b5 = (const float*)d_in[12];
    float* out = (float*)d_out;

    static int smem_set = 0;
    if (!smem_set) {
        cudaFuncSetAttribute(k_conv2, cudaFuncAttributeMaxDynamicSharedMemorySize, SMEM_GEMM);
        cudaFuncSetAttribute(k_conv3, cudaFuncAttributeMaxDynamicSharedMemorySize, SMEM_GEMM);
        cudaFuncSetAttribute(k_l45,   cudaFuncAttributeMaxDynamicSharedMemorySize, SMEM_GEMM);
        smem_set = 1;
    }

    const int nbN  = (N_NODES + 255) / 256;
    const int nbE2 = (N_EDGES / 2 + 255) / 256;
    const int nbG  = (N_NODES + GT - 1) / GT;          // 391
    const int nbW  = (N_NODES * 32 + 255) / 256;       // 1 warp per node

    // ELL build: zero cursors -> fill (cursor becomes degree) -> dinv/px prep
    k_zero<<<nbN, 256>>>();
    k_fill<<<nbE2, 256>>>(ei);
    k_prep<<<nbN, 256>>>(x);

    // conv1 aggregation (width 2)
    k_gather2<<<nbN, 256>>>();

    // conv2: expand+MMA -> g(half) ; gather -> h
    k_conv2<<<nbG, 256, SMEM_GEMM>>>(W1, b1, W2);
    k_gather<<<nbW, 256>>>(b2, 1);
    // conv3: MMA -> g(half) ; gather -> h
    k_conv3<<<nbG, 256, SMEM_GEMM>>>(W3);
    k_gather<<<nbW, 256>>>(b3, 0);
    // layers 4+5 fused
    k_l45<<<nbG, 256, SMEM_GEMM>>>(W4, b4, W5, b5, out);
}

// round 15
// speedup vs baseline: 1.2854x; 1.0661x over previous
#include <cuda_runtime.h>
#include <cuda_fp16.h>
#include <cstdint>

#define N_NODES 100000
#define N_EDGES 1000000
#define HID 64
#define CAP 64          // ELL capacity per node (P(deg>64) ~ 1e-40 at mean 10)

#define GT 256          // nodes per GEMM block tile
#define XLD 264         // Xs row stride (floats): bank-conflict-free fragment loads
#define WLD 72          // Ws row stride
#define SMEM_GEMM ((HID * XLD + HID * WLD) * 4)       // 86016 B

// Scratch (device globals: allocation-free per harness rules)
__device__ __align__(16) __half g_half[N_NODES * HID]; // transform out, fp16 (gather source)
__device__ __align__(16) __half h_half[N_NODES * HID]; // aggregated layer output, fp16
__device__ __align__(16) float px_buf[N_NODES * 2];    // dinv * x
__device__ __align__(16) float t_buf[N_NODES * 2];     // conv1 aggregated (width 2)
__device__ float dinv_buf[N_NODES];
__device__ int   cur_deg[N_NODES];                     // fill cursor == degree after fill
__device__ int   ell_row[N_NODES * CAP];               // source nodes, ELL layout

// ---------------- tf32 helpers ----------------
__device__ __forceinline__ float f2tf32f(float f) {
    uint32_t r;
    asm("cvt.rna.tf32.f32 %0, %1;" : "=r"(r) : "f"(f));
    return __uint_as_float(r);
}
// D += A(16x8,row) * B(8x8,col) ; tf32 inputs, f32 accum
__device__ __forceinline__ void mma_tf32(float* c, const uint32_t* a,
                                         uint32_t b0, uint32_t b1) {
    asm("mma.sync.aligned.m16n8k8.row.col.f32.tf32.tf32.f32 "
        "{%0,%1,%2,%3}, {%4,%5,%6,%7}, {%8,%9}, {%0,%1,%2,%3};"
        : "+f"(c[0]), "+f"(c[1]), "+f"(c[2]), "+f"(c[3])
        : "r"(a[0]), "r"(a[1]), "r"(a[2]), "r"(a[3]), "r"(b0), "r"(b1));
}

// ---------------- ELL build ----------------
__global__ void k_zero() {
    int i = blockIdx.x * blockDim.x + threadIdx.x;
    if (i < N_NODES) cur_deg[i] = 0;
}

__global__ void k_fill(const int* __restrict__ ei) {
    int e2 = (blockIdx.x * blockDim.x + threadIdx.x) * 2;
    if (e2 < N_EDGES) {
        int2 r = *(const int2*)(ei + e2);
        int2 c = *(const int2*)(ei + N_EDGES + e2);
        int p0 = atomicAdd(&cur_deg[c.x], 1);
        if (p0 < CAP) ell_row[c.x * CAP + p0] = r.x;
        int p1 = atomicAdd(&cur_deg[c.y], 1);
        if (p1 < CAP) ell_row[c.y * CAP + p1] = r.y;
    }
}

__global__ void k_prep(const float* __restrict__ x) {
    int i = blockIdx.x * blockDim.x + threadIdx.x;
    if (i < N_NODES) {
        int d = cur_deg[i];
        float di = rsqrtf((float)(d + 1));     // +1 self loop
        dinv_buf[i] = di;
        float2 xv = ((const float2*)x)[i];
        ((float2*)px_buf)[i] = make_float2(di * xv.x, di * xv.y);
    }
}

// ---------------- width-2 aggregation for conv1: 4 threads per node ----------------
__global__ void k_gather2() {
    int idx = blockIdx.x * blockDim.x + threadIdx.x;   // N_NODES*4 threads
    int i = idx >> 2;
    int q = idx & 3;
    if (i >= N_NODES) return;

    const float2* pp = (const float2*)px_buf;
    float2 acc = make_float2(0.f, 0.f);
    int d = cur_deg[i]; if (d > CAP) d = CAP;
    int s = i * CAP;
    for (int k = q; k < d; k += 4) {
        float2 v = __ldg(&pp[ell_row[s + k]]);
        acc.x += v.x; acc.y += v.y;
    }
    // combine quad (threads of one node are consecutive, quad-aligned)
    acc.x += __shfl_xor_sync(0xffffffffu, acc.x, 1);
    acc.y += __shfl_xor_sync(0xffffffffu, acc.y, 1);
    acc.x += __shfl_xor_sync(0xffffffffu, acc.x, 2);
    acc.y += __shfl_xor_sync(0xffffffffu, acc.y, 2);
    if (q == 0) {
        float2 self = pp[i];
        float di = dinv_buf[i];
        ((float2*)t_buf)[i] = make_float2(di * (acc.x + self.x), di * (acc.y + self.y));
    }
}

// ---------------- fused gather-aggregate + finalize (fp16 src, fp32 accum, fp16 dst)
__global__ void k_gather(const float* __restrict__ bias, int do_relu) {
    int w = (blockIdx.x * blockDim.x + threadIdx.x) >> 5;
    int lane = threadIdx.x & 31;
    if (w >= N_NODES) return;

    const __half2* gp = (const __half2*)g_half;
    float2 acc = __half22float2(gp[w * 32 + lane]);   // self loop
    int s = w * CAP;
    int d = cur_deg[w]; if (d > CAP) d = CAP;
    int e = s + d;

    int k = s;
    for (; k + 8 <= e; k += 8) {
        int r0 = ell_row[k],   r1 = ell_row[k+1], r2 = ell_row[k+2], r3 = ell_row[k+3];
        int r4 = ell_row[k+4], r5 = ell_row[k+5], r6 = ell_row[k+6], r7 = ell_row[k+7];
        float2 v0 = __half22float2(__ldg(&gp[r0 * 32 + lane]));
        float2 v1 = __half22float2(__ldg(&gp[r1 * 32 + lane]));
        float2 v2 = __half22float2(__ldg(&gp[r2 * 32 + lane]));
        float2 v3 = __half22float2(__ldg(&gp[r3 * 32 + lane]));
        float2 v4 = __half22float2(__ldg(&gp[r4 * 32 + lane]));
        float2 v5 = __half22float2(__ldg(&gp[r5 * 32 + lane]));
        float2 v6 = __half22float2(__ldg(&gp[r6 * 32 + lane]));
        float2 v7 = __half22float2(__ldg(&gp[r7 * 32 + lane]));
        acc.x += ((v0.x + v1.x) + (v2.x + v3.x)) + ((v4.x + v5.x) + (v6.x + v7.x));
        acc.y += ((v0.y + v1.y) + (v2.y + v3.y)) + ((v4.y + v5.y) + (v6.y + v7.y));
    }
    for (; k < e; k++) {
        float2 v = __half22float2(__ldg(&gp[ell_row[k] * 32 + lane]));
        acc.x += v.x;
        acc.y += v.y;
    }

    float di = dinv_buf[w];
    float o0 = di * acc.x + bias[lane * 2];
    float o1 = di * acc.y + bias[lane * 2 + 1];
    if (do_relu) { o0 = fmaxf(o0, 0.f); o1 = fmaxf(o1, 0.f); }
    ((__half2*)h_half)[w * 32 + lane] = __floats2half2_rn(o0, o1);
}

// ---------------- GEMM helpers (tf32 in smem, mma.m16n8k8 core) ----------------
__device__ __forceinline__ void load_W(const float* __restrict__ W, float* Ws) {
    for (int i = threadIdx.x; i < HID * HID / 4; i += 256) {
        float4 w4 = ((const float4*)W)[i];
        int k = (i * 4) >> 6, f = (i * 4) & 63;
        float* dst = Ws + k * WLD + f;
        dst[0] = f2tf32f(w4.x);
        dst[1] = f2tf32f(w4.y);
        dst[2] = f2tf32f(w4.z);
        dst[3] = f2tf32f(w4.w);
    }
}

// load X tile from h_half (fp16) transposed into tf32 k-major smem
__device__ __forceinline__ void load_X_T(int base, float* Xs) {
    int tid = threadIdx.x;
    int node = base + tid;
    if (node < N_NODES) {
        const uint2* src = (const uint2*)(h_half + node * HID);   // 4 halves per uint2
#pragma unroll
        for (int kk = 0; kk < 16; kk++) {
            uint2 u = src[kk];
            float2 a = __half22float2(*(__half2*)&u.x);
            float2 b = __half22float2(*(__half2*)&u.y);
            Xs[(kk * 4 + 0) * XLD + tid] = a.x;    // fp16 already within tf32 precision
            Xs[(kk * 4 + 1) * XLD + tid] = a.y;
            Xs[(kk * 4 + 2) * XLD + tid] = b.x;
            Xs[(kk * 4 + 3) * XLD + tid] = b.y;
        }
    } else {
#pragma unroll
        for (int kk = 0; kk < HID; kk++) Xs[kk * XLD + tid] = 0.f;
    }
}

// acc[mt][nt][4]: rows (w*32+mt*16+qr, +8), cols (nt*8+2qc, +1)
__device__ __forceinline__ void mma_core(const float* Xs, const float* Ws,
                                         float acc[2][8][4]) {
    int lane = threadIdx.x & 31, w = threadIdx.x >> 5;
    int qr = lane >> 2;       // 0..7
    int qc = lane & 3;        // 0..3
#pragma unroll
    for (int ks = 0; ks < 8; ks++) {
        uint32_t a[2][4];
#pragma unroll
        for (int mt = 0; mt < 2; mt++) {
            int rb = w * 32 + mt * 16 + qr;
            a[mt][0] = __float_as_uint(Xs[(ks * 8 + qc) * XLD + rb]);
            a[mt][1] = __float_as_uint(Xs[(ks * 8 + qc) * XLD + rb + 8]);
            a[mt][2] = __float_as_uint(Xs[(ks * 8 + qc + 4) * XLD + rb]);
            a[mt][3] = __float_as_uint(Xs[(ks * 8 + qc + 4) * XLD + rb + 8]);
        }
#pragma unroll
        for (int nt = 0; nt < 8; nt++) {
            uint32_t b0 = __float_as_uint(Ws[(ks * 8 + qc) * WLD + nt * 8 + qr]);
            uint32_t b1 = __float_as_uint(Ws[(ks * 8 + qc + 4) * WLD + nt * 8 + qr]);
            mma_tf32(acc[0][nt], a[0], b0, b1);
            mma_tf32(acc[1][nt], a[1], b0, b1);
        }
    }
}

// conv epilogue: g_half[n][f] = (half)(dinv[n] * acc)
__device__ __forceinline__ void conv_epilogue(int base, float acc[2][8][4]) {
    int lane = threadIdx.x & 31, w = threadIdx.x >> 5;
    int qr = lane >> 2, qc = lane & 3;
    __half2* gp = (__half2*)g_half;
#pragma unroll
    for (int mt = 0; mt < 2; mt++) {
        int n0 = base + w * 32 + mt * 16 + qr;
        int n1 = n0 + 8;
        float d0 = (n0 < N_NODES) ? dinv_buf[n0] : 0.f;
        float d1 = (n1 < N_NODES) ? dinv_buf[n1] : 0.f;
#pragma unroll
        for (int nt = 0; nt < 8; nt++) {
            int f2 = nt * 4 + qc;
            if (n0 < N_NODES)
                gp[n0 * 32 + f2] = __floats2half2_rn(acc[mt][nt][0] * d0, acc[mt][nt][1] * d0);
            if (n1 < N_NODES)
                gp[n1 * 32 + f2] = __floats2half2_rn(acc[mt][nt][2] * d1, acc[mt][nt][3] * d1);
        }
    }
}

// ---------------- conv2: expand t via W1 in-reg -> tf32 smem; MMA W2 -------------
__global__ __launch_bounds__(256, 2) void k_conv2(const float* __restrict__ W1,
                                                  const float* __restrict__ b1,
                                                  const float* __restrict__ W2) {
    extern __shared__ float sm[];
    float* Xs = sm;
    float* Ws = sm + HID * XLD;
    __shared__ float W1s[192];
    int tid = threadIdx.x;
    int base = blockIdx.x * GT;

    if (tid < 128) W1s[tid] = W1[tid];
    else if (tid < 192) W1s[tid] = b1[tid - 128];
    load_W(W2, Ws);

    float2 t = make_float2(0.f, 0.f);
    int node = base + tid;
    bool valid = node < N_NODES;
    if (valid) t = ((const float2*)t_buf)[node];
    __syncthreads();
#pragma unroll
    for (int k = 0; k < HID; k++) {
        float v = valid ? fmaxf(t.x * W1s[k] + t.y * W1s[64 + k] + W1s[128 + k], 0.f) : 0.f;
        Xs[k * XLD + tid] = f2tf32f(v);
    }
    __syncthreads();

    float acc[2][8][4];
#pragma unroll
    for (int mt = 0; mt < 2; mt++)
#pragma unroll
        for (int nt = 0; nt < 8; nt++)
#pragma unroll
            for (int q = 0; q < 4; q++) acc[mt][nt][q] = 0.f;
    mma_core(Xs, Ws, acc);
    conv_epilogue(base, acc);
}

// ---------------- conv3: X from h_half; MMA W3; g = dinv * X@W3 ------------------
__global__ __launch_bounds__(256, 2) void k_conv3(const float* __restrict__ W3) {
    extern __shared__ float sm[];
    float* Xs = sm;
    float* Ws = sm + HID * XLD;
    int base = blockIdx.x * GT;

    load_W(W3, Ws);
    load_X_T(base, Xs);
    __syncthreads();

    float acc[2][8][4];
#pragma unroll
    for (int mt = 0; mt < 2; mt++)
#pragma unroll
        for (int nt = 0; nt < 8; nt++)
#pragma unroll
            for (int q = 0; q < 4; q++) acc[mt][nt][q] = 0.f;
    mma_core(Xs, Ws, acc);
    conv_epilogue(base, acc);
}

// ---------------- l45: X from h_half; MMA W4; out = relu(acc+b4) . W5 + b5 -------
__global__ __launch_bounds__(256, 2) void k_l45(const float* __restrict__ W4,
                                                const float* __restrict__ b4,
                                                const float* __restrict__ W5,
                                                const float* __restrict__ b5,
                                                float* __restrict__ out) {
    extern __shared__ float sm[];
    float* Xs = sm;
    float* Ws = sm + HID * XLD;
    int tid = threadIdx.x;
    int base = blockIdx.x * GT;

    load_W(W4, Ws);
    load_X_T(base, Xs);
    __syncthreads();

    float acc[2][8][4];
#pragma unroll
    for (int mt = 0; mt < 2; mt++)
#pragma unroll
        for (int nt = 0; nt < 8; nt++)
#pragma unroll
            for (int q = 0; q < 4; q++) acc[mt][nt][q] = 0.f;
    mma_core(Xs, Ws, acc);

    int lane = tid & 31, w = tid >> 5;
    int qr = lane >> 2, qc = lane & 3;
    float bias5 = __ldg(b5);

    float b4r[8][2], w5r[8][2];
#pragma unroll
    for (int nt = 0; nt < 8; nt++) {
        int f = nt * 8 + 2 * qc;
        b4r[nt][0] = __ldg(b4 + f);     b4r[nt][1] = __ldg(b4 + f + 1);
        w5r[nt][0] = __ldg(W5 + f);     w5r[nt][1] = __ldg(W5 + f + 1);
    }

#pragma unroll
    for (int mt = 0; mt < 2; mt++) {
        float s0 = 0.f, s1 = 0.f;
#pragma unroll
        for (int nt = 0; nt < 8; nt++) {
            s0 += fmaxf(acc[mt][nt][0] + b4r[nt][0], 0.f) * w5r[nt][0]
                + fmaxf(acc[mt][nt][1] + b4r[nt][1], 0.f) * w5r[nt][1];
            s1 += fmaxf(acc[mt][nt][2] + b4r[nt][0], 0.f) * w5r[nt][0]
                + fmaxf(acc[mt][nt][3] + b4r[nt][1], 0.f) * w5r[nt][1];
        }
        s0 += __shfl_xor_sync(0xffffffffu, s0, 1);
        s0 += __shfl_xor_sync(0xffffffffu, s0, 2);
        s1 += __shfl_xor_sync(0xffffffffu, s1, 1);
        s1 += __shfl_xor_sync(0xffffffffu, s1, 2);
        if (qc == 0) {
            int n0 = base + w * 32 + mt * 16 + qr;
            int n1 = n0 + 8;
            if (n0 < N_NODES) out[n0] = s0 + bias5;
            if (n1 < N_NODES) out[n1] = s1 + bias5;
        }
    }
}

extern "C" void kernel_launch(void* const* d_in, const int* in_sizes, int n_in,
                              void* d_out, int out_size) {
    const float* x  = (const float*)d_in[0];
    const int*   ei = (const int*)d_in[1];     // edge_index int32
    const float* W1 = (const float*)d_in[3];
    const float* b1 = (const float*)d_in[4];
    const float* W2 = (const float*)d_in[5];
    const float* b2 = (const float*)d_in[6];
    const float* W3 = (const float*)d_in[7];
    const float* b3 = (const float*)d_in[8];
    const float* W4 = (const float*)d_in[9];
    const float* b4 = (const float*)d_in[10];
    const float* W5 = (const float*)d_in[11];
    const float* b5 = (const float*)d_in[12];
    float* out = (float*)d_out;

    static int smem_set = 0;
    if (!smem_set) {
        cudaFuncSetAttribute(k_conv2, cudaFuncAttributeMaxDynamicSharedMemorySize, SMEM_GEMM);
        cudaFuncSetAttribute(k_conv3, cudaFuncAttributeMaxDynamicSharedMemorySize, SMEM_GEMM);
        cudaFuncSetAttribute(k_l45,   cudaFuncAttributeMaxDynamicSharedMemorySize, SMEM_GEMM);
        smem_set = 1;
    }

    const int nbN  = (N_NODES + 255) / 256;
    const int nbN4 = (N_NODES * 4 + 255) / 256;
    const int nbE2 = (N_EDGES / 2 + 255) / 256;
    const int nbG  = (N_NODES + GT - 1) / GT;          // 391
    const int nbW  = (N_NODES * 32 + 255) / 256;       // 1 warp per node

    // ELL build: zero cursors -> fill (cursor becomes degree) -> dinv/px prep
    k_zero<<<nbN, 256>>>();
    k_fill<<<nbE2, 256>>>(ei);
    k_prep<<<nbN, 256>>>(x);

    // conv1 aggregation (width 2), 4 threads per node
    k_gather2<<<nbN4, 256>>>();

    // conv2: expand+MMA -> g(half) ; gather -> h(half)
    k_conv2<<<nbG, 256, SMEM_GEMM>>>(W1, b1, W2);
    k_gather<<<nbW, 256>>>(b2, 1);
    // conv3: MMA -> g(half) ; gather -> h(half)
    k_conv3<<<nbG, 256, SMEM_GEMM>>>(W3);
    k_gather<<<nbW, 256>>>(b3, 0);
    // layers 4+5 fused
    k_l45<<<nbG, 256, SMEM_GEMM>>>(W4, b4, W5, b5, out);
}

// round 16
// speedup vs baseline: 1.2909x; 1.0043x over previous
#include <cuda_runtime.h>
#include <cuda_fp16.h>
#include <cstdint>

#define N_NODES 100000
#define N_EDGES 1000000
#define HID 64
#define CAP 64          // ELL capacity per node (P(deg>64) ~ 1e-40 at mean 10)

#define GT 256          // nodes per GEMM block tile
#define XLD 264         // Xs row stride (floats): bank-conflict-free fragment loads
#define WLD 72          // Ws row stride
#define SMEM_GEMM ((HID * XLD + HID * WLD) * 4)       // 86016 B

// Scratch (device globals: allocation-free per harness rules; zero-initialized at load)
__device__ __align__(16) __half g_half[N_NODES * HID]; // transform out, fp16 (gather source)
__device__ __align__(16) __half h_half[N_NODES * HID]; // aggregated layer output, fp16
__device__ __align__(16) float px_buf[N_NODES * 2];    // dinv * x
__device__ __align__(16) float t_buf[N_NODES * 2];     // conv1 aggregated (width 2)
__device__ float dinv_buf[N_NODES];
__device__ int   cur_deg[N_NODES];                     // fill cursor == degree; re-zeroed by k_l45
__device__ int   ell_row[N_NODES * CAP];               // source nodes, ELL layout

// ---------------- tf32 helpers ----------------
__device__ __forceinline__ float f2tf32f(float f) {
    uint32_t r;
    asm("cvt.rna.tf32.f32 %0, %1;" : "=r"(r) : "f"(f));
    return __uint_as_float(r);
}
// D += A(16x8,row) * B(8x8,col) ; tf32 inputs, f32 accum
__device__ __forceinline__ void mma_tf32(float* c, const uint32_t* a,
                                         uint32_t b0, uint32_t b1) {
    asm("mma.sync.aligned.m16n8k8.row.col.f32.tf32.tf32.f32 "
        "{%0,%1,%2,%3}, {%4,%5,%6,%7}, {%8,%9}, {%0,%1,%2,%3};"
        : "+f"(c[0]), "+f"(c[1]), "+f"(c[2]), "+f"(c[3])
        : "r"(a[0]), "r"(a[1]), "r"(a[2]), "r"(a[3]), "r"(b0), "r"(b1));
}

// ---------------- ELL build (cur_deg pre-zeroed: module load / previous k_l45) ----
__global__ void k_fill(const int* __restrict__ ei) {
    int e4 = (blockIdx.x * blockDim.x + threadIdx.x) * 4;
    if (e4 + 3 < N_EDGES) {
        int4 r = *(const int4*)(ei + e4);
        int4 c = *(const int4*)(ei + N_EDGES + e4);
        int p0 = atomicAdd(&cur_deg[c.x], 1);
        int p1 = atomicAdd(&cur_deg[c.y], 1);
        int p2 = atomicAdd(&cur_deg[c.z], 1);
        int p3 = atomicAdd(&cur_deg[c.w], 1);
        if (p0 < CAP) ell_row[c.x * CAP + p0] = r.x;
        if (p1 < CAP) ell_row[c.y * CAP + p1] = r.y;
        if (p2 < CAP) ell_row[c.z * CAP + p2] = r.z;
        if (p3 < CAP) ell_row[c.w * CAP + p3] = r.w;
    } else if (e4 < N_EDGES) {
        for (int e = e4; e < N_EDGES; e++) {
            int rr = ei[e], cc = ei[N_EDGES + e];
            int p = atomicAdd(&cur_deg[cc], 1);
            if (p < CAP) ell_row[cc * CAP + p] = rr;
        }
    }
}

__global__ void k_prep(const float* __restrict__ x) {
    int i = blockIdx.x * blockDim.x + threadIdx.x;
    if (i < N_NODES) {
        int d = cur_deg[i];
        float di = rsqrtf((float)(d + 1));     // +1 self loop
        dinv_buf[i] = di;
        float2 xv = ((const float2*)x)[i];
        ((float2*)px_buf)[i] = make_float2(di * xv.x, di * xv.y);
    }
}

// ---------------- width-2 aggregation for conv1: 8 threads per node ----------------
__global__ void k_gather2() {
    int idx = blockIdx.x * blockDim.x + threadIdx.x;   // N_NODES*8 threads
    int i = idx >> 3;
    int q = idx & 7;
    if (i >= N_NODES) return;

    const float2* pp = (const float2*)px_buf;
    float2 acc = make_float2(0.f, 0.f);
    int d = cur_deg[i]; if (d > CAP) d = CAP;
    int s = i * CAP;
    for (int k = q; k < d; k += 8) {
        float2 v = __ldg(&pp[ell_row[s + k]]);
        acc.x += v.x; acc.y += v.y;
    }
    // combine octet (threads of one node are consecutive, octet-aligned)
    acc.x += __shfl_xor_sync(0xffffffffu, acc.x, 1);
    acc.y += __shfl_xor_sync(0xffffffffu, acc.y, 1);
    acc.x += __shfl_xor_sync(0xffffffffu, acc.x, 2);
    acc.y += __shfl_xor_sync(0xffffffffu, acc.y, 2);
    acc.x += __shfl_xor_sync(0xffffffffu, acc.x, 4);
    acc.y += __shfl_xor_sync(0xffffffffu, acc.y, 4);
    if (q == 0) {
        float2 self = pp[i];
        float di = dinv_buf[i];
        ((float2*)t_buf)[i] = make_float2(di * (acc.x + self.x), di * (acc.y + self.y));
    }
}

// ---------------- fused gather-aggregate + finalize (fp16 src, fp32 accum, fp16 dst)
__global__ void k_gather(const float* __restrict__ bias, int do_relu) {
    int w = (blockIdx.x * blockDim.x + threadIdx.x) >> 5;
    int lane = threadIdx.x & 31;
    if (w >= N_NODES) return;

    const __half2* gp = (const __half2*)g_half;
    float2 acc = __half22float2(gp[w * 32 + lane]);   // self loop
    int s = w * CAP;
    int d = cur_deg[w]; if (d > CAP) d = CAP;
    int e = s + d;

    int k = s;
    for (; k + 8 <= e; k += 8) {
        int r0 = ell_row[k],   r1 = ell_row[k+1], r2 = ell_row[k+2], r3 = ell_row[k+3];
        int r4 = ell_row[k+4], r5 = ell_row[k+5], r6 = ell_row[k+6], r7 = ell_row[k+7];
        float2 v0 = __half22float2(__ldg(&gp[r0 * 32 + lane]));
        float2 v1 = __half22float2(__ldg(&gp[r1 * 32 + lane]));
        float2 v2 = __half22float2(__ldg(&gp[r2 * 32 + lane]));
        float2 v3 = __half22float2(__ldg(&gp[r3 * 32 + lane]));
        float2 v4 = __half22float2(__ldg(&gp[r4 * 32 + lane]));
        float2 v5 = __half22float2(__ldg(&gp[r5 * 32 + lane]));
        float2 v6 = __half22float2(__ldg(&gp[r6 * 32 + lane]));
        float2 v7 = __half22float2(__ldg(&gp[r7 * 32 + lane]));
        acc.x += ((v0.x + v1.x) + (v2.x + v3.x)) + ((v4.x + v5.x) + (v6.x + v7.x));
        acc.y += ((v0.y + v1.y) + (v2.y + v3.y)) + ((v4.y + v5.y) + (v6.y + v7.y));
    }
    for (; k < e; k++) {
        float2 v = __half22float2(__ldg(&gp[ell_row[k] * 32 + lane]));
        acc.x += v.x;
        acc.y += v.y;
    }

    float di = dinv_buf[w];
    float o0 = di * acc.x + bias[lane * 2];
    float o1 = di * acc.y + bias[lane * 2 + 1];
    if (do_relu) { o0 = fmaxf(o0, 0.f); o1 = fmaxf(o1, 0.f); }
    ((__half2*)h_half)[w * 32 + lane] = __floats2half2_rn(o0, o1);
}

// ---------------- GEMM helpers (tf32 in smem, mma.m16n8k8 core) ----------------
__device__ __forceinline__ void load_W(const float* __restrict__ W, float* Ws) {
    for (int i = threadIdx.x; i < HID * HID / 4; i += 256) {
        float4 w4 = ((const float4*)W)[i];
        int k = (i * 4) >> 6, f = (i * 4) & 63;
        float* dst = Ws + k * WLD + f;
        dst[0] = f2tf32f(w4.x);
        dst[1] = f2tf32f(w4.y);
        dst[2] = f2tf32f(w4.z);
        dst[3] = f2tf32f(w4.w);
    }
}

// load X tile from h_half (fp16) transposed into tf32 k-major smem
__device__ __forceinline__ void load_X_T(int base, float* Xs) {
    int tid = threadIdx.x;
    int node = base + tid;
    if (node < N_NODES) {
        const uint2* src = (const uint2*)(h_half + node * HID);   // 4 halves per uint2
#pragma unroll
        for (int kk = 0; kk < 16; kk++) {
            uint2 u = src[kk];
            float2 a = __half22float2(*(__half2*)&u.x);
            float2 b = __half22float2(*(__half2*)&u.y);
            Xs[(kk * 4 + 0) * XLD + tid] = a.x;
            Xs[(kk * 4 + 1) * XLD + tid] = a.y;
            Xs[(kk * 4 + 2) * XLD + tid] = b.x;
            Xs[(kk * 4 + 3) * XLD + tid] = b.y;
        }
    } else {
#pragma unroll
        for (int kk = 0; kk < HID; kk++) Xs[kk * XLD + tid] = 0.f;
    }
}

// acc[mt][nt][4]: rows (w*32+mt*16+qr, +8), cols (nt*8+2qc, +1)
__device__ __forceinline__ void mma_core(const float* Xs, const float* Ws,
                                         float acc[2][8][4]) {
    int lane = threadIdx.x & 31, w = threadIdx.x >> 5;
    int qr = lane >> 2;       // 0..7
    int qc = lane & 3;        // 0..3
#pragma unroll
    for (int ks = 0; ks < 8; ks++) {
        uint32_t a[2][4];
#pragma unroll
        for (int mt = 0; mt < 2; mt++) {
            int rb = w * 32 + mt * 16 + qr;
            a[mt][0] = __float_as_uint(Xs[(ks * 8 + qc) * XLD + rb]);
            a[mt][1] = __float_as_uint(Xs[(ks * 8 + qc) * XLD + rb + 8]);
            a[mt][2] = __float_as_uint(Xs[(ks * 8 + qc + 4) * XLD + rb]);
            a[mt][3] = __float_as_uint(Xs[(ks * 8 + qc + 4) * XLD + rb + 8]);
        }
#pragma unroll
        for (int nt = 0; nt < 8; nt++) {
            uint32_t b0 = __float_as_uint(Ws[(ks * 8 + qc) * WLD + nt * 8 + qr]);
            uint32_t b1 = __float_as_uint(Ws[(ks * 8 + qc + 4) * WLD + nt * 8 + qr]);
            mma_tf32(acc[0][nt], a[0], b0, b1);
            mma_tf32(acc[1][nt], a[1], b0, b1);
        }
    }
}

// conv epilogue: g_half[n][f] = (half)(dinv[n] * acc)
__device__ __forceinline__ void conv_epilogue(int base, float acc[2][8][4]) {
    int lane = threadIdx.x & 31, w = threadIdx.x >> 5;
    int qr = lane >> 2, qc = lane & 3;
    __half2* gp = (__half2*)g_half;
#pragma unroll
    for (int mt = 0; mt < 2; mt++) {
        int n0 = base + w * 32 + mt * 16 + qr;
        int n1 = n0 + 8;
        float d0 = (n0 < N_NODES) ? dinv_buf[n0] : 0.f;
        float d1 = (n1 < N_NODES) ? dinv_buf[n1] : 0.f;
#pragma unroll
        for (int nt = 0; nt < 8; nt++) {
            int f2 = nt * 4 + qc;
            if (n0 < N_NODES)
                gp[n0 * 32 + f2] = __floats2half2_rn(acc[mt][nt][0] * d0, acc[mt][nt][1] * d0);
            if (n1 < N_NODES)
                gp[n1 * 32 + f2] = __floats2half2_rn(acc[mt][nt][2] * d1, acc[mt][nt][3] * d1);
        }
    }
}

// ---------------- conv2: expand t via W1 in-reg -> tf32 smem; MMA W2 -------------
__global__ __launch_bounds__(256, 2) void k_conv2(const float* __restrict__ W1,
                                                  const float* __restrict__ b1,
                                                  const float* __restrict__ W2) {
    extern __shared__ float sm[];
    float* Xs = sm;
    float* Ws = sm + HID * XLD;
    __shared__ float W1s[192];
    int tid = threadIdx.x;
    int base = blockIdx.x * GT;

    if (tid < 128) W1s[tid] = W1[tid];
    else if (tid < 192) W1s[tid] = b1[tid - 128];
    load_W(W2, Ws);

    float2 t = make_float2(0.f, 0.f);
    int node = base + tid;
    bool valid = node < N_NODES;
    if (valid) t = ((const float2*)t_buf)[node];
    __syncthreads();
#pragma unroll
    for (int k = 0; k < HID; k++) {
        float v = valid ? fmaxf(t.x * W1s[k] + t.y * W1s[64 + k] + W1s[128 + k], 0.f) : 0.f;
        Xs[k * XLD + tid] = f2tf32f(v);
    }
    __syncthreads();

    float acc[2][8][4];
#pragma unroll
    for (int mt = 0; mt < 2; mt++)
#pragma unroll
        for (int nt = 0; nt < 8; nt++)
#pragma unroll
            for (int q = 0; q < 4; q++) acc[mt][nt][q] = 0.f;
    mma_core(Xs, Ws, acc);
    conv_epilogue(base, acc);
}

// ---------------- conv3: X from h_half; MMA W3; g = dinv * X@W3 ------------------
__global__ __launch_bounds__(256, 2) void k_conv3(const float* __restrict__ W3) {
    extern __shared__ float sm[];
    float* Xs = sm;
    float* Ws = sm + HID * XLD;
    int base = blockIdx.x * GT;

    load_W(W3, Ws);
    load_X_T(base, Xs);
    __syncthreads();

    float acc[2][8][4];
#pragma unroll
    for (int mt = 0; mt < 2; mt++)
#pragma unroll
        for (int nt = 0; nt < 8; nt++)
#pragma unroll
            for (int q = 0; q < 4; q++) acc[mt][nt][q] = 0.f;
    mma_core(Xs, Ws, acc);
    conv_epilogue(base, acc);
}

// ---------------- l45: X from h_half; MMA W4; out = relu(acc+b4) . W5 + b5 -------
// Also re-zeros cur_deg for the next graph replay (deterministic: zero at entry
// of every run because module-load zero-init + this end-of-run reset).
__global__ __launch_bounds__(256, 2) void k_l45(const float* __restrict__ W4,
                                                const float* __restrict__ b4,
                                                const float* __restrict__ W5,
                                                const float* __restrict__ b5,
                                                float* __restrict__ out) {
    extern __shared__ float sm[];
    float* Xs = sm;
    float* Ws = sm + HID * XLD;
    int tid = threadIdx.x;
    int base = blockIdx.x * GT;

    load_W(W4, Ws);
    load_X_T(base, Xs);
    __syncthreads();

    float acc[2][8][4];
#pragma unroll
    for (int mt = 0; mt < 2; mt++)
#pragma unroll
        for (int nt = 0; nt < 8; nt++)
#pragma unroll
            for (int q = 0; q < 4; q++) acc[mt][nt][q] = 0.f;
    mma_core(Xs, Ws, acc);

    int lane = tid & 31, w = tid >> 5;
    int qr = lane >> 2, qc = lane & 3;
    float bias5 = __ldg(b5);

    float b4r[8][2], w5r[8][2];
#pragma unroll
    for (int nt = 0; nt < 8; nt++) {
        int f = nt * 8 + 2 * qc;
        b4r[nt][0] = __ldg(b4 + f);     b4r[nt][1] = __ldg(b4 + f + 1);
        w5r[nt][0] = __ldg(W5 + f);     w5r[nt][1] = __ldg(W5 + f + 1);
    }

#pragma unroll
    for (int mt = 0; mt < 2; mt++) {
        float s0 = 0.f, s1 = 0.f;
#pragma unroll
        for (int nt = 0; nt < 8; nt++) {
            s0 += fmaxf(acc[mt][nt][0] + b4r[nt][0], 0.f) * w5r[nt][0]
                + fmaxf(acc[mt][nt][1] + b4r[nt][1], 0.f) * w5r[nt][1];
            s1 += fmaxf(acc[mt][nt][2] + b4r[nt][0], 0.f) * w5r[nt][0]
                + fmaxf(acc[mt][nt][3] + b4r[nt][1], 0.f) * w5r[nt][1];
        }
        s0 += __shfl_xor_sync(0xffffffffu, s0, 1);
        s0 += __shfl_xor_sync(0xffffffffu, s0, 2);
        s1 += __shfl_xor_sync(0xffffffffu, s1, 1);
        s1 += __shfl_xor_sync(0xffffffffu, s1, 2);
        if (qc == 0) {
            int n0 = base + w * 32 + mt * 16 + qr;
            int n1 = n0 + 8;
            if (n0 < N_NODES) out[n0] = s0 + bias5;
            if (n1 < N_NODES) out[n1] = s1 + bias5;
        }
    }

    // reset cur_deg for next replay (after last read this run)
    int node = base + tid;
    if (node < N_NODES) cur_deg[node] = 0;
}

extern "C" void kernel_launch(void* const* d_in, const int* in_sizes, int n_in,
                              void* d_out, int out_size) {
    const float* x  = (const float*)d_in[0];
    const int*   ei = (const int*)d_in[1];     // edge_index int32
    const float* W1 = (const float*)d_in[3];
    const float* b1 = (const float*)d_in[4];
    const float* W2 = (const float*)d_in[5];
    const float* b2 = (const float*)d_in[6];
    const float* W3 = (const float*)d_in[7];
    const float* b3 = (const float*)d_in[8];
    const float* W4 = (const float*)d_in[9];
    const float* b4 = (const float*)d_in[10];
    const float* W5 = (const float*)d_in[11];
    const float* b5 = (const float*)d_in[12];
    float* out = (float*)d_out;

    static int smem_set = 0;
    if (!smem_set) {
        cudaFuncSetAttribute(k_conv2, cudaFuncAttributeMaxDynamicSharedMemorySize, SMEM_GEMM);
        cudaFuncSetAttribute(k_conv3, cudaFuncAttributeMaxDynamicSharedMemorySize, SMEM_GEMM);
        cudaFuncSetAttribute(k_l45,   cudaFuncAttributeMaxDynamicSharedMemorySize, SMEM_GEMM);
        smem_set = 1;
    }

    const int nbN  = (N_NODES + 255) / 256;
    const int nbN8 = (N_NODES * 8 + 255) / 256;
    const int nbE4 = (N_EDGES / 4 + 255) / 256;
    const int nbG  = (N_NODES + GT - 1) / GT;          // 391
    const int nbW  = (N_NODES * 32 + 255) / 256;       // 1 warp per node

    // ELL build (cur_deg enters zeroed) -> dinv/px prep
    k_fill<<<nbE4, 256>>>(ei);
    k_prep<<<nbN, 256>>>(x);

    // conv1 aggregation (width 2), 8 threads per node
    k_gather2<<<nbN8, 256>>>();

    // conv2: expand+MMA -> g(half) ; gather -> h(half)
    k_conv2<<<nbG, 256, SMEM_GEMM>>>(W1, b1, W2);
    k_gather<<<nbW, 256>>>(b2, 1);
    // conv3: MMA -> g(half) ; gather -> h(half)
    k_conv3<<<nbG, 256, SMEM_GEMM>>>(W3);
    k_gather<<<nbW, 256>>>(b3, 0);
    // layers 4+5 fused (+ cur_deg reset for next replay)
    k_l45<<<nbG, 256, SMEM_GEMM>>>(W4, b4, W5, b5, out);
}

// round 17
// speedup vs baseline: 1.3392x; 1.0374x over previous
#include <cuda_runtime.h>
#include <cuda_fp16.h>
#include <cstdint>

#define N_NODES 100000
#define N_EDGES 1000000
#define HID 64
#define CAP 64          // ELL capacity per node (P(deg>64) ~ 1e-40 at mean 10)

#define GT 256          // nodes per GEMM block tile
#define XLDH 72         // Xs row stride (halves): 144B rows -> ldmatrix conflict-free
#define WLDH 72         // Ws row stride (halves)
#define SMEM_GEMM ((GT * XLDH + HID * WLDH) * 2)      // 46080 B (< 48KB default)

// Scratch (device globals: allocation-free per harness rules; zero-initialized at load)
__device__ __align__(16) __half g_half[N_NODES * HID]; // transform out, fp16 (gather source)
__device__ __align__(16) __half h_half[N_NODES * HID]; // aggregated layer output, fp16
__device__ __align__(16) float px_buf[N_NODES * 2];    // dinv * x
__device__ __align__(16) float t_buf[N_NODES * 2];     // conv1 aggregated (width 2)
__device__ float dinv_buf[N_NODES];
__device__ int   cur_deg[N_NODES];                     // fill cursor == degree; re-zeroed by k_l45
__device__ int   ell_row[N_NODES * CAP];               // source nodes, ELL layout

// ---------------- mma/ldmatrix helpers ----------------
__device__ __forceinline__ uint32_t smem_u32(const void* p) {
    return (uint32_t)__cvta_generic_to_shared(p);
}
__device__ __forceinline__ void ldm_x4(uint32_t* r, uint32_t addr) {
    asm volatile("ldmatrix.sync.aligned.m8n8.x4.shared.b16 {%0,%1,%2,%3}, [%4];"
                 : "=r"(r[0]), "=r"(r[1]), "=r"(r[2]), "=r"(r[3]) : "r"(addr));
}
// D += A(16x16,row) * B(16x8,col) ; f16 inputs, f32 accum
__device__ __forceinline__ void mma_f16(float* c, const uint32_t* a,
                                        uint32_t b0, uint32_t b1) {
    asm volatile("mma.sync.aligned.m16n8k16.row.col.f32.f16.f16.f32 "
                 "{%0,%1,%2,%3},{%4,%5,%6,%7},{%8,%9},{%0,%1,%2,%3};"
                 : "+f"(c[0]), "+f"(c[1]), "+f"(c[2]), "+f"(c[3])
                 : "r"(a[0]), "r"(a[1]), "r"(a[2]), "r"(a[3]), "r"(b0), "r"(b1));
}

// ---------------- ELL build (cur_deg pre-zeroed: module load / previous k_l45) ----
__global__ void k_fill(const int* __restrict__ ei) {
    int e4 = (blockIdx.x * blockDim.x + threadIdx.x) * 4;
    if (e4 + 3 < N_EDGES) {
        int4 r = *(const int4*)(ei + e4);
        int4 c = *(const int4*)(ei + N_EDGES + e4);
        int p0 = atomicAdd(&cur_deg[c.x], 1);
        int p1 = atomicAdd(&cur_deg[c.y], 1);
        int p2 = atomicAdd(&cur_deg[c.z], 1);
        int p3 = atomicAdd(&cur_deg[c.w], 1);
        if (p0 < CAP) ell_row[c.x * CAP + p0] = r.x;
        if (p1 < CAP) ell_row[c.y * CAP + p1] = r.y;
        if (p2 < CAP) ell_row[c.z * CAP + p2] = r.z;
        if (p3 < CAP) ell_row[c.w * CAP + p3] = r.w;
    } else if (e4 < N_EDGES) {
        for (int e = e4; e < N_EDGES; e++) {
            int rr = ei[e], cc = ei[N_EDGES + e];
            int p = atomicAdd(&cur_deg[cc], 1);
            if (p < CAP) ell_row[cc * CAP + p] = rr;
        }
    }
}

__global__ void k_prep(const float* __restrict__ x) {
    int i = blockIdx.x * blockDim.x + threadIdx.x;
    if (i < N_NODES) {
        int d = cur_deg[i];
        float di = rsqrtf((float)(d + 1));     // +1 self loop
        dinv_buf[i] = di;
        float2 xv = ((const float2*)x)[i];
        ((float2*)px_buf)[i] = make_float2(di * xv.x, di * xv.y);
    }
}

// ---------------- width-2 aggregation for conv1: 8 threads per node ----------------
__global__ void k_gather2() {
    int idx = blockIdx.x * blockDim.x + threadIdx.x;   // N_NODES*8 threads
    int i = idx >> 3;
    int q = idx & 7;
    if (i >= N_NODES) return;

    const float2* pp = (const float2*)px_buf;
    float2 acc = make_float2(0.f, 0.f);
    int d = cur_deg[i]; if (d > CAP) d = CAP;
    int s = i * CAP;
    for (int k = q; k < d; k += 8) {
        float2 v = __ldg(&pp[ell_row[s + k]]);
        acc.x += v.x; acc.y += v.y;
    }
    acc.x += __shfl_xor_sync(0xffffffffu, acc.x, 1);
    acc.y += __shfl_xor_sync(0xffffffffu, acc.y, 1);
    acc.x += __shfl_xor_sync(0xffffffffu, acc.x, 2);
    acc.y += __shfl_xor_sync(0xffffffffu, acc.y, 2);
    acc.x += __shfl_xor_sync(0xffffffffu, acc.x, 4);
    acc.y += __shfl_xor_sync(0xffffffffu, acc.y, 4);
    if (q == 0) {
        float2 self = pp[i];
        float di = dinv_buf[i];
        ((float2*)t_buf)[i] = make_float2(di * (acc.x + self.x), di * (acc.y + self.y));
    }
}

// ---------------- fused gather-aggregate + finalize (fp16 src, fp32 accum, fp16 dst)
__global__ void k_gather(const float* __restrict__ bias, int do_relu) {
    int w = (blockIdx.x * blockDim.x + threadIdx.x) >> 5;
    int lane = threadIdx.x & 31;
    if (w >= N_NODES) return;

    const __half2* gp = (const __half2*)g_half;
    float2 acc = __half22float2(gp[w * 32 + lane]);   // self loop
    int s = w * CAP;
    int d = cur_deg[w]; if (d > CAP) d = CAP;
    int e = s + d;

    int k = s;
    for (; k + 8 <= e; k += 8) {
        int r0 = ell_row[k],   r1 = ell_row[k+1], r2 = ell_row[k+2], r3 = ell_row[k+3];
        int r4 = ell_row[k+4], r5 = ell_row[k+5], r6 = ell_row[k+6], r7 = ell_row[k+7];
        float2 v0 = __half22float2(__ldg(&gp[r0 * 32 + lane]));
        float2 v1 = __half22float2(__ldg(&gp[r1 * 32 + lane]));
        float2 v2 = __half22float2(__ldg(&gp[r2 * 32 + lane]));
        float2 v3 = __half22float2(__ldg(&gp[r3 * 32 + lane]));
        float2 v4 = __half22float2(__ldg(&gp[r4 * 32 + lane]));
        float2 v5 = __half22float2(__ldg(&gp[r5 * 32 + lane]));
        float2 v6 = __half22float2(__ldg(&gp[r6 * 32 + lane]));
        float2 v7 = __half22float2(__ldg(&gp[r7 * 32 + lane]));
        acc.x += ((v0.x + v1.x) + (v2.x + v3.x)) + ((v4.x + v5.x) + (v6.x + v7.x));
        acc.y += ((v0.y + v1.y) + (v2.y + v3.y)) + ((v4.y + v5.y) + (v6.y + v7.y));
    }
    for (; k < e; k++) {
        float2 v = __half22float2(__ldg(&gp[ell_row[k] * 32 + lane]));
        acc.x += v.x;
        acc.y += v.y;
    }

    float di = dinv_buf[w];
    float o0 = di * acc.x + bias[lane * 2];
    float o1 = di * acc.y + bias[lane * 2 + 1];
    if (do_relu) { o0 = fmaxf(o0, 0.f); o1 = fmaxf(o1, 0.f); }
    ((__half2*)h_half)[w * 32 + lane] = __floats2half2_rn(o0, o1);
}

// ---------------- GEMM helpers (fp16 smem, ldmatrix + m16n8k16 HMMA) -------------
// W global is [k][n] row-major; store transposed as Ws[n][k] halves (col-major B).
__device__ __forceinline__ void load_W_T(const float* __restrict__ W, __half* Ws) {
    for (int i = threadIdx.x; i < HID * HID / 4; i += 256) {
        int k = i >> 4;
        int n4 = (i & 15) * 4;
        float4 w4 = ((const float4*)W)[i];   // W[k][n4..n4+3]
        Ws[(n4 + 0) * WLDH + k] = __float2half_rn(w4.x);
        Ws[(n4 + 1) * WLDH + k] = __float2half_rn(w4.y);
        Ws[(n4 + 2) * WLDH + k] = __float2half_rn(w4.z);
        Ws[(n4 + 3) * WLDH + k] = __float2half_rn(w4.w);
    }
}

// Copy X tile rows (already fp16, node-major) into padded smem rows.
__device__ __forceinline__ void load_X_h(int base, __half* Xs) {
    int tid = threadIdx.x;
    int node = base + tid;
    float4* dst = (float4*)(Xs + tid * XLDH);            // 144B rows, 16B aligned
    if (node < N_NODES) {
        const float4* src = (const float4*)(h_half + node * HID);
#pragma unroll
        for (int q = 0; q < 8; q++) dst[q] = src[q];
    } else {
#pragma unroll
        for (int q = 0; q < 8; q++) dst[q] = make_float4(0.f, 0.f, 0.f, 0.f);
    }
}

// acc[mt][nt][4]: c0,c1 = row (w*32+mt*16+g), cols nt*8+2t,2t+1 ; c2,c3 = row +8
__device__ __forceinline__ void mma_core(const __half* Xs, const __half* Ws,
                                         float acc[2][8][4]) {
    int lane = threadIdx.x & 31, w = threadIdx.x >> 5;
    int j = lane & 7, mi = lane >> 3;

    uint32_t abase[2];
#pragma unroll
    for (int mt = 0; mt < 2; mt++) {
        int row = w * 32 + mt * 16 + j + (mi & 1) * 8;
        int koff = (mi >> 1) * 8;
        abase[mt] = smem_u32(Xs + row * XLDH + koff);
    }
    uint32_t bbase[4];
#pragma unroll
    for (int p = 0; p < 4; p++) {
        int n = p * 16 + (mi >> 1) * 8 + j;
        int koff = (mi & 1) * 8;
        bbase[p] = smem_u32(Ws + n * WLDH + koff);
    }

#pragma unroll
    for (int ks = 0; ks < 4; ks++) {
        uint32_t a[2][4];
        ldm_x4(a[0], abase[0] + ks * 32);
        ldm_x4(a[1], abase[1] + ks * 32);
#pragma unroll
        for (int p = 0; p < 4; p++) {
            uint32_t b[4];                     // {b0_nt, b1_nt, b0_nt+1, b1_nt+1}
            ldm_x4(b, bbase[p] + ks * 32);
            mma_f16(acc[0][2*p],     a[0], b[0], b[1]);
            mma_f16(acc[1][2*p],     a[1], b[0], b[1]);
            mma_f16(acc[0][2*p + 1], a[0], b[2], b[3]);
            mma_f16(acc[1][2*p + 1], a[1], b[2], b[3]);
        }
    }
}

// conv epilogue: g_half[n][f] = (half)(dinv[n] * acc)
__device__ __forceinline__ void conv_epilogue(int base, float acc[2][8][4]) {
    int lane = threadIdx.x & 31, w = threadIdx.x >> 5;
    int g = lane >> 2, t = lane & 3;
    __half2* gp = (__half2*)g_half;
#pragma unroll
    for (int mt = 0; mt < 2; mt++) {
        int n0 = base + w * 32 + mt * 16 + g;
        int n1 = n0 + 8;
        float d0 = (n0 < N_NODES) ? dinv_buf[n0] : 0.f;
        float d1 = (n1 < N_NODES) ? dinv_buf[n1] : 0.f;
#pragma unroll
        for (int nt = 0; nt < 8; nt++) {
            int f2 = nt * 4 + t;
            if (n0 < N_NODES)
                gp[n0 * 32 + f2] = __floats2half2_rn(acc[mt][nt][0] * d0, acc[mt][nt][1] * d0);
            if (n1 < N_NODES)
                gp[n1 * 32 + f2] = __floats2half2_rn(acc[mt][nt][2] * d1, acc[mt][nt][3] * d1);
        }
    }
}

// ---------------- conv2: expand t via W1 in-reg -> fp16 smem; HMMA W2 ------------
__global__ __launch_bounds__(256, 2) void k_conv2(const float* __restrict__ W1,
                                                  const float* __restrict__ b1,
                                                  const float* __restrict__ W2) {
    extern __shared__ __half smh[];
    __half* Xs = smh;
    __half* Ws = smh + GT * XLDH;
    __shared__ float W1s[192];
    int tid = threadIdx.x;
    int base = blockIdx.x * GT;

    if (tid < 128) W1s[tid] = W1[tid];
    else if (tid < 192) W1s[tid] = b1[tid - 128];
    load_W_T(W2, Ws);

    float2 tv = make_float2(0.f, 0.f);
    int node = base + tid;
    bool valid = node < N_NODES;
    if (valid) tv = ((const float2*)t_buf)[node];
    __syncthreads();                 // W1s ready
    {
        __half2* xrow = (__half2*)(Xs + tid * XLDH);
#pragma unroll
        for (int k2 = 0; k2 < 32; k2++) {
            float v0 = 0.f, v1 = 0.f;
            if (valid) {
                v0 = fmaxf(tv.x * W1s[2*k2]   + tv.y * W1s[64 + 2*k2]   + W1s[128 + 2*k2],   0.f);
                v1 = fmaxf(tv.x * W1s[2*k2+1] + tv.y * W1s[64 + 2*k2+1] + W1s[128 + 2*k2+1], 0.f);
            }
            xrow[k2] = __floats2half2_rn(v0, v1);
        }
    }
    __syncthreads();

    float acc[2][8][4];
#pragma unroll
    for (int mt = 0; mt < 2; mt++)
#pragma unroll
        for (int nt = 0; nt < 8; nt++)
#pragma unroll
            for (int q = 0; q < 4; q++) acc[mt][nt][q] = 0.f;
    mma_core(Xs, Ws, acc);
    conv_epilogue(base, acc);
}

// ---------------- conv3: X from h_half; HMMA W3; g = dinv * X@W3 -----------------
__global__ __launch_bounds__(256, 2) void k_conv3(const float* __restrict__ W3) {
    extern __shared__ __half smh[];
    __half* Xs = smh;
    __half* Ws = smh + GT * XLDH;
    int base = blockIdx.x * GT;

    load_W_T(W3, Ws);
    load_X_h(base, Xs);
    __syncthreads();

    float acc[2][8][4];
#pragma unroll
    for (int mt = 0; mt < 2; mt++)
#pragma unroll
        for (int nt = 0; nt < 8; nt++)
#pragma unroll
            for (int q = 0; q < 4; q++) acc[mt][nt][q] = 0.f;
    mma_core(Xs, Ws, acc);
    conv_epilogue(base, acc);
}

// ---------------- l45: X from h_half; HMMA W4; out = relu(acc+b4) . W5 + b5 ------
// Also re-zeros cur_deg for the next graph replay.
__global__ __launch_bounds__(256, 2) void k_l45(const float* __restrict__ W4,
                                                const float* __restrict__ b4,
                                                const float* __restrict__ W5,
                                                const float* __restrict__ b5,
                                                float* __restrict__ out) {
    extern __shared__ __half smh[];
    __half* Xs = smh;
    __half* Ws = smh + GT * XLDH;
    int tid = threadIdx.x;
    int base = blockIdx.x * GT;

    load_W_T(W4, Ws);
    load_X_h(base, Xs);
    __syncthreads();

    float acc[2][8][4];
#pragma unroll
    for (int mt = 0; mt < 2; mt++)
#pragma unroll
        for (int nt = 0; nt < 8; nt++)
#pragma unroll
            for (int q = 0; q < 4; q++) acc[mt][nt][q] = 0.f;
    mma_core(Xs, Ws, acc);

    int lane = tid & 31, w = tid >> 5;
    int g = lane >> 2, t = lane & 3;
    float bias5 = __ldg(b5);

    float b4r[8][2], w5r[8][2];
#pragma unroll
    for (int nt = 0; nt < 8; nt++) {
        int f = nt * 8 + 2 * t;
        b4r[nt][0] = __ldg(b4 + f);     b4r[nt][1] = __ldg(b4 + f + 1);
        w5r[nt][0] = __ldg(W5 + f);     w5r[nt][1] = __ldg(W5 + f + 1);
    }

#pragma unroll
    for (int mt = 0; mt < 2; mt++) {
        float s0 = 0.f, s1 = 0.f;
#pragma unroll
        for (int nt = 0; nt < 8; nt++) {
            s0 += fmaxf(acc[mt][nt][0] + b4r[nt][0], 0.f) * w5r[nt][0]
                + fmaxf(acc[mt][nt][1] + b4r[nt][1], 0.f) * w5r[nt][1];
            s1 += fmaxf(acc[mt][nt][2] + b4r[nt][0], 0.f) * w5r[nt][0]
                + fmaxf(acc[mt][nt][3] + b4r[nt][1], 0.f) * w5r[nt][1];
        }
        s0 += __shfl_xor_sync(0xffffffffu, s0, 1);
        s0 += __shfl_xor_sync(0xffffffffu, s0, 2);
        s1 += __shfl_xor_sync(0xffffffffu, s1, 1);
        s1 += __shfl_xor_sync(0xffffffffu, s1, 2);
        if (t == 0) {
            int n0 = base + w * 32 + mt * 16 + g;
            int n1 = n0 + 8;
            if (n0 < N_NODES) out[n0] = s0 + bias5;
            if (n1 < N_NODES) out[n1] = s1 + bias5;
        }
    }

    // reset cur_deg for next replay (after last read this run)
    int node = base + tid;
    if (node < N_NODES) cur_deg[node] = 0;
}

extern "C" void kernel_launch(void* const* d_in, const int* in_sizes, int n_in,
                              void* d_out, int out_size) {
    const float* x  = (const float*)d_in[0];
    const int*   ei = (const int*)d_in[1];     // edge_index int32
    const float* W1 = (const float*)d_in[3];
    const float* b1 = (const float*)d_in[4];
    const float* W2 = (const float*)d_in[5];
    const float* b2 = (const float*)d_in[6];
    const float* W3 = (const float*)d_in[7];
    const float* b3 = (const float*)d_in[8];
    const float* W4 = (const float*)d_in[9];
    const float* b4 = (const float*)d_in[10];
    const float* W5 = (const float*)d_in[11];
    const float* b5 = (const float*)d_in[12];
    float* out = (float*)d_out;

    const int nbN  = (N_NODES + 255) / 256;
    const int nbN8 = (N_NODES * 8 + 255) / 256;
    const int nbE4 = (N_EDGES / 4 + 255) / 256;
    const int nbG  = (N_NODES + GT - 1) / GT;          // 391
    const int nbW  = (N_NODES * 32 + 255) / 256;       // 1 warp per node

    // ELL build (cur_deg enters zeroed) -> dinv/px prep
    k_fill<<<nbE4, 256>>>(ei);
    k_prep<<<nbN, 256>>>(x);

    // conv1 aggregation (width 2), 8 threads per node
    k_gather2<<<nbN8, 256>>>();

    // conv2: expand+HMMA -> g(half) ; gather -> h(half)
    k_conv2<<<nbG, 256, SMEM_GEMM>>>(W1, b1, W2);
    k_gather<<<nbW, 256>>>(b2, 1);
    // conv3: HMMA -> g(half) ; gather -> h(half)
    k_conv3<<<nbG, 256, SMEM_GEMM>>>(W3);
    k_gather<<<nbW, 256>>>(b3, 0);
    // layers 4+5 fused (+ cur_deg reset for next replay)
    k_l45<<<nbG, 256, SMEM_GEMM>>>(W4, b4, W5, b5, out);
}